// round 17
// baseline (speedup 1.0000x reference)
#include <cuda_runtime.h>
#include <cuda_bf16.h>
#include <cstdint>
#include <cfloat>

#define BHn 64
#define TQn 1024
#define TKn 1024
#define DKn 64
#define SCST 1028
#define MB_NEG -30000.0f

__device__ __nv_bfloat16 g_Qh[BHn*TQn*DKn], g_Ql[BHn*TQn*DKn];
__device__ __nv_bfloat16 g_Kh[BHn*TKn*DKn], g_Kl[BHn*TKn*DKn];
__device__ __nv_bfloat16 g_VTh[BHn*DKn*TKn], g_VTl[BHn*DKn*TKn];
__device__ int g_mask_narrow;

// ---------------- helpers ----------------
__device__ __forceinline__ unsigned su32(const void* p){ return (unsigned)__cvta_generic_to_shared(p); }
__device__ __forceinline__ void cp16(unsigned d, const void* s){ asm volatile("cp.async.cg.shared.global [%0], [%1], 16;" :: "r"(d), "l"(s)); }
#define CPC()  asm volatile("cp.async.commit_group;")
#define CPW0() asm volatile("cp.async.wait_group 0;" ::: "memory")
#define CPW1() asm volatile("cp.async.wait_group 1;" ::: "memory")

__device__ __forceinline__ void ldm4(unsigned* r, unsigned a){
    asm volatile("ldmatrix.sync.aligned.m8n8.x4.shared.b16 {%0,%1,%2,%3}, [%4];"
        : "=r"(r[0]),"=r"(r[1]),"=r"(r[2]),"=r"(r[3]) : "r"(a));
}
__device__ __forceinline__ void ldm2(unsigned* r, unsigned a){
    asm volatile("ldmatrix.sync.aligned.m8n8.x2.shared.b16 {%0,%1}, [%2];"
        : "=r"(r[0]),"=r"(r[1]) : "r"(a));
}
__device__ __forceinline__ void mma16816(float* c, const unsigned* a, const unsigned* b){
    asm volatile("mma.sync.aligned.m16n8k16.row.col.f32.bf16.bf16.f32 "
        "{%0,%1,%2,%3}, {%4,%5,%6,%7}, {%8,%9}, {%0,%1,%2,%3};"
        : "+f"(c[0]),"+f"(c[1]),"+f"(c[2]),"+f"(c[3])
        : "r"(a[0]),"r"(a[1]),"r"(a[2]),"r"(a[3]), "r"(b[0]),"r"(b[1]));
}

// ---------------- prep kernels ----------------
__global__ void detect_mask_kernel(const unsigned int* __restrict__ mw) {
    __shared__ int found;
    if (threadIdx.x == 0) found = 0;
    __syncthreads();
    int local = 0;
    for (int i = threadIdx.x; i < (BHn * TKn) / 4; i += blockDim.x)
        if (mw[i] & 0xFFFFFF00u) local = 1;
    if (local) atomicOr(&found, 1);
    __syncthreads();
    if (threadIdx.x == 0) g_mask_narrow = found;
}

__global__ void split_qk_kernel(const float* __restrict__ Q, const float* __restrict__ K) {
    int n = BHn * TQn * DKn;
    for (int i = blockIdx.x * blockDim.x + threadIdx.x; i < n; i += gridDim.x * blockDim.x) {
        float q = Q[i]; __nv_bfloat16 h = __float2bfloat16(q);
        g_Qh[i] = h; g_Ql[i] = __float2bfloat16(q - __bfloat162float(h));
        float k = K[i]; h = __float2bfloat16(k);
        g_Kh[i] = h; g_Kl[i] = __float2bfloat16(k - __bfloat162float(h));
    }
}

__global__ void transpose_v_kernel(const float* __restrict__ V) {
    __shared__ float tile[32][33];
    int bh = blockIdx.z, k0 = blockIdx.x * 32, d0 = blockIdx.y * 32;
    const float* Vb = V + (size_t)bh * TKn * DKn;
    for (int r = threadIdx.y; r < 32; r += 8)
        tile[r][threadIdx.x] = Vb[(size_t)(k0 + r) * DKn + d0 + threadIdx.x];
    __syncthreads();
    for (int r = threadIdx.y; r < 32; r += 8) {
        float v = tile[threadIdx.x][r];
        __nv_bfloat16 h = __float2bfloat16(v);
        size_t o = (size_t)bh * DKn * TKn + (size_t)(d0 + r) * TKn + k0 + threadIdx.x;
        g_VTh[o] = h; g_VTl[o] = __float2bfloat16(v - __bfloat162float(h));
    }
}

// ====== fused kernel: e = exp(QK/8 + bias) -> row sums -> W store + O = W@V ======
// phase A smem: QH 0 (4608) | QL 4608 | K 9216 + buf*36864 (..82944)
// phase B smem (reuses [0,82944)): WCONV 0 (2 x 9216: hi 4608 + lo 4608) | VT 18432 (2 x 18432)
// persistent: SC 82944 (131584) | MB 214528 | PART 218624 | INV 219648 -> 219776
#define S1_QH 0
#define S1_QL 4608
#define S1_KB 9216
#define B_W   0
#define B_VT  18432
#define S1_SC 82944
#define S1_MB 214528
#define S1_PART 218624
#define S1_INV 219648
#define SMEM1 219776
#define NT1 512

__device__ __forceinline__ void k1_stage_k(unsigned sb, const __nv_bfloat16* kh,
                                           const __nv_bfloat16* kl, int kt, int buf, int t) {
    unsigned base = sb + S1_KB + buf * 36864;
    const __nv_bfloat16* sh = kh + (size_t)kt * 128 * 64;
    const __nv_bfloat16* sl = kl + (size_t)kt * 128 * 64;
    #pragma unroll
    for (int i = 0; i < 2; i++) {
        int idx = t + i * NT1, r = idx >> 3, c = idx & 7;
        cp16(base + r * 144 + c * 16, sh + (size_t)r * 64 + c * 8);
        cp16(base + 18432 + r * 144 + c * 16, sl + (size_t)r * 64 + c * 8);
    }
    CPC();
}

extern "C" __global__ void __launch_bounds__(NT1, 1)
attn_fused_kernel(const unsigned char* __restrict__ Mb, const int* __restrict__ pHA,
                  const int* __restrict__ pNH, float* __restrict__ Wout,
                  float* __restrict__ O)
{
    extern __shared__ char sm[];
    float* scsh  = (float*)(sm + S1_SC);
    float* mb    = (float*)(sm + S1_MB);
    float* part  = (float*)(sm + S1_PART);
    float* invsh = (float*)(sm + S1_INV);

    const int t = threadIdx.x, w = t >> 5, l = t & 31;
    const int bh = blockIdx.y, q0 = blockIdx.x * 32;
    float* wbase = Wout + ((size_t)bh * TQn + q0) * TKn;
    float* obase = O + ((size_t)bh * TQn + q0) * DKn;

    if (pNH[0] > 0 && (bh % pNH[0]) == pHA[0]) {
        float4 z = make_float4(0.f, 0.f, 0.f, 0.f);
        float4* w4 = (float4*)wbase;
        #pragma unroll 4
        for (int i = t; i < 32 * TKn / 4; i += NT1) w4[i] = z;
        ((float4*)obase)[t] = z;              // 512 f4 = 32x64
        return;
    }
    unsigned sb = su32(sm);
    const __nv_bfloat16* qh = g_Qh + ((size_t)bh * TQn + q0) * DKn;
    const __nv_bfloat16* ql = g_Ql + ((size_t)bh * TQn + q0) * DKn;
    const __nv_bfloat16* kh = g_Kh + (size_t)bh * TKn * DKn;
    const __nv_bfloat16* kl = g_Kl + (size_t)bh * TKn * DKn;
    const __nv_bfloat16* vth = g_VTh + (size_t)bh * DKn * TKn;
    const __nv_bfloat16* vtl = g_VTl + (size_t)bh * DKn * TKn;

    if (t < 256) {
        int r = t >> 3, c = t & 7;
        cp16(sb + S1_QH + r * 144 + c * 16, qh + (size_t)r * 64 + c * 8);
        cp16(sb + S1_QL + r * 144 + c * 16, ql + (size_t)r * 64 + c * 8);
    }
    k1_stage_k(sb, kh, kl, 0, 0, t);
    k1_stage_k(sb, kh, kl, 1, 1, t);

    const int shift = g_mask_narrow ? 0 : 2;
    const unsigned char* mrow = Mb + (((size_t)bh * TKn) << shift);
    #pragma unroll
    for (int i = 0; i < 2; i++) {
        int k = t + i * NT1;
        mb[k] = mrow[(size_t)k << shift] ? 0.f : MB_NEG;
    }

    // ================= phase A: e = exp(QK/8 + bias) =================
    const int qhx = w >> 3, ks = w & 7;
    const int l2 = l & 15, g = l >> 2, j = l & 3;
    const unsigned qa_h = sb + S1_QH + (16 * qhx + (l & 15)) * 144 + (l >> 4) * 16;
    const unsigned qa_l = qa_h + (S1_QL - S1_QH);
    unsigned ah[4][4], al[4][4];
    float s_lo = 0.f, s_hi = 0.f;

    for (int kt = 0; kt < 8; kt++) {
        int b = kt & 1;
        if (kt < 7) CPW1(); else CPW0();
        __syncthreads();
        if (kt == 0) {
            #pragma unroll
            for (int s = 0; s < 4; s++) { ldm4(ah[s], qa_h + s * 32); ldm4(al[s], qa_l + s * 32); }
        }
        unsigned kb = sb + S1_KB + b * 36864;
        #pragma unroll
        for (int nt = 0; nt < 2; nt++) {
            unsigned baddr = kb + (ks * 16 + nt * 8 + (l2 & 7)) * 144 + (l2 >> 3) * 16;
            unsigned bh_[4][2], bl_[4][2];
            #pragma unroll
            for (int s = 0; s < 4; s++) { ldm2(bh_[s], baddr + s * 32); ldm2(bl_[s], baddr + 18432 + s * 32); }
            float c[4] = {0.f, 0.f, 0.f, 0.f};
            #pragma unroll
            for (int s = 0; s < 4; s++) mma16816(c, ah[s], bh_[s]);
            #pragma unroll
            for (int s = 0; s < 4; s++) mma16816(c, ah[s], bl_[s]);
            #pragma unroll
            for (int s = 0; s < 4; s++) mma16816(c, al[s], bh_[s]);
            int kloc = kt * 128 + ks * 16 + nt * 8 + 2 * j;
            float2 mbv = *(const float2*)&mb[kloc];
            float e00 = __expf(fmaf(c[0], 0.125f, mbv.x));
            float e01 = __expf(fmaf(c[1], 0.125f, mbv.y));
            float e10 = __expf(fmaf(c[2], 0.125f, mbv.x));
            float e11 = __expf(fmaf(c[3], 0.125f, mbv.y));
            s_lo += e00 + e01; s_hi += e10 + e11;
            float* p = scsh + (size_t)(16 * qhx + g) * SCST + kloc;
            *(float2*)p = make_float2(e00, e01);
            *(float2*)(p + 8 * SCST) = make_float2(e10, e11);
        }
        __syncthreads();
        if (kt < 6) k1_stage_k(sb, kh, kl, kt + 2, b, t);
    }

    // ---- row sums -> inv ----
    s_lo += __shfl_xor_sync(0xffffffffu, s_lo, 1);
    s_lo += __shfl_xor_sync(0xffffffffu, s_lo, 2);
    s_hi += __shfl_xor_sync(0xffffffffu, s_hi, 1);
    s_hi += __shfl_xor_sync(0xffffffffu, s_hi, 2);
    if (j == 0) {
        part[w * 16 + g] = s_lo;
        part[w * 16 + 8 + g] = s_hi;
    }
    __syncthreads();
    if (t < 32) {
        int qhh = t >> 4, g2 = t & 15;
        float s = 0.f;
        #pragma unroll
        for (int k2 = 0; k2 < 8; k2++) s += part[(qhh * 8 + k2) * 16 + g2];
        invsh[t] = (s == 0.f) ? 0.f : __frcp_rn(s);
    }
    __syncthreads();

    // ================= phase B: W store + O = W @ V =================
    // convert chunk kt (32q x 64k): scale e by inv, STG W, split bf16 hi/lo -> wconv buf b
    auto convert_w = [&](int b, int kt) {
        int q = t >> 4, c4 = t & 15;
        float inv = invsh[q];
        float4 x = *(const float4*)&scsh[(size_t)q * SCST + kt * 64 + c4 * 4];
        x.x *= inv; x.y *= inv; x.z *= inv; x.w *= inv;
        *(float4*)(wbase + (size_t)q * TKn + kt * 64 + c4 * 4) = x;
        __nv_bfloat16 h0 = __float2bfloat16(x.x), h1 = __float2bfloat16(x.y);
        __nv_bfloat16 h2 = __float2bfloat16(x.z), h3 = __float2bfloat16(x.w);
        char* d = sm + B_W + b * 9216 + q * 144 + c4 * 8;
        *(__nv_bfloat162*)d = __halves2bfloat162(h0, h1);
        *(__nv_bfloat162*)(d + 4) = __halves2bfloat162(h2, h3);
        *(__nv_bfloat162*)(d + 4608) = __halves2bfloat162(
            __float2bfloat16(x.x - __bfloat162float(h0)), __float2bfloat16(x.y - __bfloat162float(h1)));
        *(__nv_bfloat162*)(d + 4608 + 4) = __halves2bfloat162(
            __float2bfloat16(x.z - __bfloat162float(h2)), __float2bfloat16(x.w - __bfloat162float(h3)));
    };
    // stage VT chunk kt (64d x 64k, hi+lo) into buf b
    auto stage_vt = [&](int b, int kt) {
        unsigned base = sb + B_VT + b * 18432;
        int r = t >> 3, c = t & 7;
        cp16(base + r * 144 + c * 16, vth + (size_t)r * TKn + kt * 64 + c * 8);
        cp16(base + 9216 + r * 144 + c * 16, vtl + (size_t)r * TKn + kt * 64 + c * 8);
        CPC();
    };

    stage_vt(0, 0);
    convert_w(0, 0);
    CPW0();
    __syncthreads();

    // warp grid: qhx (2 q-halves) x ds = w&7 (8 d-slices of 8)
    const int ds = w & 7;
    float co[4] = {0.f, 0.f, 0.f, 0.f};

    for (int kt = 0; kt < 16; kt++) {
        int b = kt & 1;
        if (kt < 15) { stage_vt(b ^ 1, kt + 1); convert_w(b ^ 1, kt + 1); }

        unsigned wb2 = sb + B_W + b * 9216;
        unsigned vb2 = sb + B_VT + b * 18432;
        unsigned aaddr = wb2 + (16 * qhx + (l & 15)) * 144 + (l >> 4) * 16;
        unsigned baddr = vb2 + (ds * 8 + (l2 & 7)) * 144 + (l2 >> 3) * 16;
        #pragma unroll
        for (int s = 0; s < 4; s++) {
            unsigned ahx[4], alx[4], bhx[2], blx[2];
            ldm4(ahx, aaddr + s * 32);
            ldm4(alx, aaddr + 4608 + s * 32);
            ldm2(bhx, baddr + s * 32);
            ldm2(blx, baddr + 9216 + s * 32);
            mma16816(co, ahx, bhx);
            mma16816(co, ahx, blx);
            mma16816(co, alx, bhx);
        }

        if (kt < 15) {
            CPW0();
            __syncthreads();
        }
    }

    // epilogue: O store (warp = 16q x 8d tile)
    float* o0 = obase + (size_t)(16 * qhx + g) * DKn + ds * 8 + 2 * j;
    *(float2*)o0 = make_float2(co[0], co[1]);
    *(float2*)(o0 + 8 * DKn) = make_float2(co[2], co[3]);
}

// ---------------------------------------------------------------------------
extern "C" void kernel_launch(void* const* d_in, const int* in_sizes, int n_in,
                              void* d_out, int out_size) {
    const float*         Q  = (const float*)d_in[0];
    const float*         K  = (const float*)d_in[1];
    const float*         V  = (const float*)d_in[2];
    const unsigned char* Mb = (const unsigned char*)d_in[3];
    const int*           HA = (const int*)d_in[4];
    const int*           NH = (const int*)d_in[5];
    float*               O  = (float*)d_out;
    float*               W  = O + (size_t)BHn * TQn * DKn;

    cudaFuncSetAttribute(attn_fused_kernel, cudaFuncAttributeMaxDynamicSharedMemorySize, SMEM1);

    detect_mask_kernel<<<1, 256>>>((const unsigned int*)Mb);
    split_qk_kernel<<<2048, 256>>>(Q, K);
    transpose_v_kernel<<<dim3(32, 2, 64), dim3(32, 8)>>>(V);
    attn_fused_kernel<<<dim3(32, 64), NT1, SMEM1>>>(Mb, HA, NH, W, O);
}